// round 15
// baseline (speedup 1.0000x reference)
#include <cuda_runtime.h>
#include <cuda_fp16.h>
#include <math.h>
#include <stdint.h>

#define BATCH   4
#define SEQLEN  4096
#define DIM     512
#define DINNER  1024
#define DSTATE  16
#define DCONV   4
#define M_TOK   (BATCH*SEQLEN)   // 16384

// ======================= PTX helpers (sm_80 baseline) ========================
__device__ __forceinline__ uint32_t smem_to_u32(const void* p) {
    uint32_t a;
    asm("{ .reg .u64 t; cvta.to.shared.u64 t, %1; cvt.u32.u64 %0, t; }"
        : "=r"(a) : "l"(p));
    return a;
}
#define CP_ASYNC16(saddr, gptr) \
    asm volatile("cp.async.cg.shared.global [%0], [%1], 16;" \
        :: "r"(saddr), "l"(gptr))
#define CP_COMMIT() asm volatile("cp.async.commit_group;" ::: "memory")
#define CP_WAIT1()  asm volatile("cp.async.wait_group 1;" ::: "memory")
#define CP_WAIT0()  asm volatile("cp.async.wait_group 0;" ::: "memory")

#define LDSM_X4(r, addr) \
    asm volatile("ldmatrix.sync.aligned.m8n8.x4.shared.b16 {%0,%1,%2,%3}, [%4];" \
        : "=r"((r)[0]), "=r"((r)[1]), "=r"((r)[2]), "=r"((r)[3]) : "r"(addr))

#define MMA_F16(d, a, b0, b1) \
    asm volatile("mma.sync.aligned.m16n8k16.row.col.f32.f16.f16.f32 " \
        "{%0,%1,%2,%3}, {%4,%5,%6,%7}, {%8,%9}, {%0,%1,%2,%3};" \
        : "+f"((d)[0]), "+f"((d)[1]), "+f"((d)[2]), "+f"((d)[3]) \
        : "r"((a)[0]), "r"((a)[1]), "r"((a)[2]), "r"((a)[3]), "r"(b0), "r"(b1))

// ======================= scratch =============================================
__device__ __align__(256) float  g_u   [M_TOK];
__device__ __align__(256) float  g_adisc[(size_t)M_TOK * DSTATE];
__device__ __align__(256) float  g_bu  [(size_t)M_TOK * DSTATE];
__device__ __align__(256) float  g_y   [(size_t)M_TOK * DSTATE];
// fp16 planes
__device__ __align__(256) __half g_xh  [(size_t)M_TOK * DIM];
__device__ __align__(256) __half g_xih [(size_t)M_TOK * DINNER];
__device__ __align__(256) __half g_resh[(size_t)M_TOK * DINNER];
__device__ __align__(256) __half g_xah [(size_t)M_TOK * DINNER];
__device__ __align__(256) __half g_yh  [(size_t)M_TOK * DINNER];
__device__ __align__(256) __half g_wih [(size_t)2*DINNER * DIM];
__device__ __align__(256) __half g_woh [(size_t)DIM * DINNER];
__device__ __align__(256) __half g_wch [2 * DSTATE * DINNER];
// scan constants
#define SCHUNK  128
#define NCHUNK  (SEQLEN / SCHUNK)   // 32

// ======================= HMMA fp16 GEMM ======================================
// Block tile 128x128, 256 threads (8 warps 4x2, warp tile 32x64),
// K-chunk 64, 3-stage cp.async pipeline, 1 sync/chunk, strength-reduced
// addressing, fragment double-buffer across ks.
// MODE 0: fp32 C. MODE 1: write g_xih. MODE 2: silu -> g_resh.
#define LG_ROWB   144
#define A_OFF_B   0
#define B_OFF_B   (128 * LG_ROWB)          // 18432
#define STAGE_B   (2 * 128 * LG_ROWB)      // 36864 per stage
#define GH_SMEM   (3 * STAGE_B)            // 110592

template<int MODE>
__global__ __launch_bounds__(256, 2)
void gemm_hmma(const __half* __restrict__ A, const __half* __restrict__ B,
               float* __restrict__ C, int Nglob, int K, int m_off)
{
    extern __shared__ char smem[];
    const uint32_t sb = smem_to_u32(smem);
    const int tid  = threadIdx.x;
    const int wid  = tid >> 5;
    const int lane = tid & 31;
    const int m0 = m_off + blockIdx.y * 128;
    const int n0 = blockIdx.x * 128;
    const int nch = K / 64;

    const int wm = (wid & 3) * 32;
    const int wn = (wid >> 2) * 64;

    float acc[2][8][4];
#pragma unroll
    for (int i = 0; i < 2; i++)
#pragma unroll
        for (int j = 0; j < 8; j++)
#pragma unroll
            for (int k = 0; k < 4; k++) acc[i][j][k] = 0.f;

    // ---- strength-reduced cp.async state (issue order is sequential) ----
    const int ld_row = tid >> 3, ld_cc = tid & 7;
    const __half* pA = A + (size_t)m0 * K + (size_t)ld_row * K + ld_cc * 8;
    const __half* pB = B + (size_t)n0 * K + (size_t)ld_row * K + ld_cc * 8;
    const uint32_t dstA = sb + (uint32_t)(ld_row * LG_ROWB + ld_cc * 16);
    const uint32_t dstB = dstA + B_OFF_B;

    auto issue = [&](int s) {
        const uint32_t so = (uint32_t)(s * STAGE_B);
#pragma unroll
        for (int i = 0; i < 4; i++) {
            CP_ASYNC16(dstA + so + (uint32_t)(i * 32 * LG_ROWB), pA + (size_t)i * 32 * K);
            CP_ASYNC16(dstB + so + (uint32_t)(i * 32 * LG_ROWB), pB + (size_t)i * 32 * K);
        }
        CP_COMMIT();
        pA += 64; pB += 64;
    };

    issue(0);
    if (nch > 1) issue(1);

    // ---- precomputed per-warp LDSM offsets (relative to stage base) ----
    const int lrow = lane & 15;
    const int lcol = (lane >> 4) * 16;
    const uint32_t aO0 = (uint32_t)((wm + lrow) * LG_ROWB + lcol);
    const uint32_t aO1 = aO0 + 16 * LG_ROWB;
    const uint32_t bO0 = (uint32_t)(B_OFF_B + (wn + lrow) * LG_ROWB + lcol);
    const uint32_t bO1 = bO0 + 16 * LG_ROWB;
    const uint32_t bO2 = bO1 + 16 * LG_ROWB;
    const uint32_t bO3 = bO2 + 16 * LG_ROWB;

    uint32_t stOff = 0;
    for (int c = 0; c < nch; c++) {
        if (c + 1 < nch) { CP_WAIT1(); } else { CP_WAIT0(); }
        __syncthreads();

        const uint32_t base = sb + stOff;
        uint32_t af[2][2][4], bf[2][4][4];

        // fragments for ks=0
        LDSM_X4(af[0][0], base + aO0);
        LDSM_X4(af[0][1], base + aO1);
        LDSM_X4(bf[0][0], base + bO0);
        LDSM_X4(bf[0][1], base + bO1);
        LDSM_X4(bf[0][2], base + bO2);
        LDSM_X4(bf[0][3], base + bO3);

        // start chunk c+2 loads early (stage read at c-1; safe after this sync)
        if (c + 2 < nch) {
            int s2 = stOff == 0 ? 2 : (stOff == STAGE_B ? 0 : 1);
            issue(s2);
        }

#pragma unroll
        for (int ks = 0; ks < 4; ks++) {
            const int cur = ks & 1, nxt = cur ^ 1;
            if (ks < 3) {   // prefetch ks+1 fragments during this ks's MMAs
                const uint32_t ko = (uint32_t)((ks + 1) * 32);
                LDSM_X4(af[nxt][0], base + aO0 + ko);
                LDSM_X4(af[nxt][1], base + aO1 + ko);
                LDSM_X4(bf[nxt][0], base + bO0 + ko);
                LDSM_X4(bf[nxt][1], base + bO1 + ko);
                LDSM_X4(bf[nxt][2], base + bO2 + ko);
                LDSM_X4(bf[nxt][3], base + bO3 + ko);
            }
#pragma unroll
            for (int mt = 0; mt < 2; mt++)
#pragma unroll
                for (int nt = 0; nt < 8; nt++) {
                    const int ng = nt >> 1, hi = nt & 1;
                    MMA_F16(acc[mt][nt], af[cur][mt], bf[cur][ng][hi], bf[cur][ng][2 + hi]);
                }
        }
        stOff = (stOff == 2 * STAGE_B) ? 0u : stOff + STAGE_B;
    }

    const int er = lane >> 2;
    const int ec = (lane & 3) * 2;
#pragma unroll
    for (int mt = 0; mt < 2; mt++) {
        const int rbase = m0 + wm + mt * 16;
#pragma unroll
        for (int nt = 0; nt < 8; nt++) {
            const int col = n0 + wn + nt * 8 + ec;
            float v0 = acc[mt][nt][0], v1 = acc[mt][nt][1];
            float v2 = acc[mt][nt][2], v3 = acc[mt][nt][3];
            if (MODE == 0) {
                *reinterpret_cast<float2*>(C + (size_t)(rbase + er)     * Nglob + col) =
                    make_float2(v0, v1);
                *reinterpret_cast<float2*>(C + (size_t)(rbase + er + 8) * Nglob + col) =
                    make_float2(v2, v3);
            } else if (MODE == 1) {
                *reinterpret_cast<__half2*>(g_xih + (size_t)(rbase + er)     * DINNER + col) =
                    __floats2half2_rn(v0, v1);
                *reinterpret_cast<__half2*>(g_xih + (size_t)(rbase + er + 8) * DINNER + col) =
                    __floats2half2_rn(v2, v3);
            } else {
                v0 = v0 / (1.f + expf(-v0));
                v1 = v1 / (1.f + expf(-v1));
                v2 = v2 / (1.f + expf(-v2));
                v3 = v3 / (1.f + expf(-v3));
                *reinterpret_cast<__half2*>(g_resh + (size_t)(rbase + er)     * DINNER + col) =
                    __floats2half2_rn(v0, v1);
                *reinterpret_cast<__half2*>(g_resh + (size_t)(rbase + er + 8) * DINNER + col) =
                    __floats2half2_rn(v2, v3);
            }
        }
    }
}

// ============== small HMMA GEMM fused with dt/A_disc/Bu epilogue =============
#define SB_ROWB   2064
#define SB_BYTES  (32 * SB_ROWB)              // 66048
#define SA_TILE   (128 * LG_ROWB)             // 18432
#define GS_SMEM   (SB_BYTES + 3 * SA_TILE)    // 121344

__global__ __launch_bounds__(256, 1)
void gemm_small(const __half* __restrict__ A, const __half* __restrict__ B,
                const float* __restrict__ bdt, const float* __restrict__ Alog)
{
    extern __shared__ char smem[];
    const uint32_t sb = smem_to_u32(smem);
    const int tid  = threadIdx.x;
    const int wid  = tid >> 5;
    const int lane = tid & 31;
    const int m0 = blockIdx.x * 128;
    const int K = DINNER;
    const int nch = K / 64;

    {
#pragma unroll
        for (int i = 0; i < 16; i++) {
            int idx = tid + i * 256;
            int row = idx >> 7, cc = idx & 127;
            CP_ASYNC16(sb + (uint32_t)(row * SB_ROWB + cc * 16),
                       B + (size_t)row * K + cc * 8);
        }
        CP_COMMIT();
    }

    const int ld_row = tid >> 3, ld_cc = tid & 7;
    const __half* pA = A + (size_t)m0 * K + (size_t)ld_row * K + ld_cc * 8;
    const uint32_t dstA = sb + (uint32_t)(SB_BYTES + ld_row * LG_ROWB + ld_cc * 16);

    auto issueA = [&](int s) {
        const uint32_t so = (uint32_t)(s * SA_TILE);
#pragma unroll
        for (int i = 0; i < 4; i++)
            CP_ASYNC16(dstA + so + (uint32_t)(i * 32 * LG_ROWB), pA + (size_t)i * 32 * K);
        CP_COMMIT();
        pA += 64;
    };

    const int wm = wid * 16;
    float acc[4][4];
#pragma unroll
    for (int j = 0; j < 4; j++)
#pragma unroll
        for (int k = 0; k < 4; k++) acc[j][k] = 0.f;

    issueA(0);
    issueA(1);

    int stage = 0;
    for (int c = 0; c < nch; c++) {
        if (c + 1 < nch) { CP_WAIT1(); } else { CP_WAIT0(); }
        __syncthreads();

        const uint32_t aBase = sb + (uint32_t)(SB_BYTES + stage * SA_TILE);
        const int lrow = lane & 15;
        const int lcol = (lane >> 4) * 16;
        if (c + 2 < nch) issueA((stage + 2) % 3);
#pragma unroll
        for (int ks = 0; ks < 4; ks++) {
            uint32_t af[4], bfr[2][4];
            LDSM_X4(af, aBase + (uint32_t)((wm + lrow) * LG_ROWB + ks*32 + lcol));
#pragma unroll
            for (int ng = 0; ng < 2; ng++)
                LDSM_X4(bfr[ng], sb + (uint32_t)((ng*16 + lrow) * SB_ROWB + (c*4 + ks)*32 + lcol));
#pragma unroll
            for (int nt = 0; nt < 4; nt++) {
                const int ng = nt >> 1, hi = nt & 1;
                MMA_F16(acc[nt], af, bfr[ng][hi], bfr[ng][2 + hi]);
            }
        }
        stage = (stage + 1) % 3;
    }

    const int er = lane >> 2;
    const int ec = (lane & 3) * 2;
    const int r0 = m0 + wm + er;
    const float u0 = g_u[r0];
    const float u1 = g_u[r0 + 8];
#pragma unroll
    for (int nt = 0; nt < 2; nt++) {
#pragma unroll
        for (int j = 0; j < 2; j++) {
            const int n = nt * 8 + ec + j;
            const float A = -expf(Alog[n]);
            const float bn = bdt[n];
            {
                float raw = acc[nt][j] + bn;
                float dt  = raw > 20.f ? raw : log1pf(expf(raw));
                g_adisc[(size_t)r0 * DSTATE + n] = expf(A * dt);
                g_bu   [(size_t)r0 * DSTATE + n] = dt * acc[nt + 2][j] * u0;
            }
            {
                float raw = acc[nt][2 + j] + bn;
                float dt  = raw > 20.f ? raw : log1pf(expf(raw));
                g_adisc[(size_t)(r0 + 8) * DSTATE + n] = expf(A * dt);
                g_bu   [(size_t)(r0 + 8) * DSTATE + n] = dt * acc[nt + 2][2 + j] * u1;
            }
        }
    }
}

// ======================= prep kernels ========================================
__global__ void prep_x_kernel(const float* __restrict__ x)
{
    long i = ((long)blockIdx.x * 256 + threadIdx.x) * 4;
    float4 v = *reinterpret_cast<const float4*>(x + i);
    *reinterpret_cast<__half2*>(g_xh + i)     = __floats2half2_rn(v.x, v.y);
    *reinterpret_cast<__half2*>(g_xh + i + 2) = __floats2half2_rn(v.z, v.w);
}
__global__ void prep_w_kernel(const float* __restrict__ W_in, const float* __restrict__ W_out,
                              const float* __restrict__ Wx, const float* __restrict__ Wdt)
{
    const int b = blockIdx.x;
    if (b < 1024) {
        long i = ((long)b * 256 + threadIdx.x) * 4;
        float4 v = *reinterpret_cast<const float4*>(W_in + i);
        *reinterpret_cast<__half2*>(g_wih + i)     = __floats2half2_rn(v.x, v.y);
        *reinterpret_cast<__half2*>(g_wih + i + 2) = __floats2half2_rn(v.z, v.w);
    } else if (b < 1536) {
        long i = ((long)(b - 1024) * 256 + threadIdx.x) * 4;
        float4 v = *reinterpret_cast<const float4*>(W_out + i);
        *reinterpret_cast<__half2*>(g_woh + i)     = __floats2half2_rn(v.x, v.y);
        *reinterpret_cast<__half2*>(g_woh + i + 2) = __floats2half2_rn(v.z, v.w);
    } else {
        int i = (b - 1536) * 1024 + threadIdx.x * 4;
        int row = i >> 10;
        const float* src = (row < DSTATE) ? Wdt : Wx;
        float4 v = *reinterpret_cast<const float4*>(src + i);
        *reinterpret_cast<__half2*>(g_wch + i)     = __floats2half2_rn(v.x, v.y);
        *reinterpret_cast<__half2*>(g_wch + i + 2) = __floats2half2_rn(v.z, v.w);
    }
}

// ======================= conv: rolling window, coalesced =====================
#define CONV_T 32
__global__ __launch_bounds__(256)
void conv_silu_kernel(const float* __restrict__ cw, const float* __restrict__ cb)
{
    const int c4 = threadIdx.x;
    const int c  = c4 * 4;
    const int t0 = blockIdx.x * CONV_T;
    const int l0 = t0 & (SEQLEN - 1);

    float w[4][4];
#pragma unroll
    for (int j = 0; j < 4; j++)
        *reinterpret_cast<float4*>(w[j]) =
            *reinterpret_cast<const float4*>(cw + (size_t)(c + j) * DCONV);
    const float4 bias = *reinterpret_cast<const float4*>(cb + c);

    auto loadrow = [&](int t) -> float4 {
        const __half* xp = g_xih + (size_t)t * DINNER + c;
        float2 f0 = __half22float2(*reinterpret_cast<const __half2*>(xp));
        float2 f1 = __half22float2(*reinterpret_cast<const __half2*>(xp + 2));
        return make_float4(f0.x, f0.y, f1.x, f1.y);
    };

    float4 h0, h1, h2;
    if (l0 != 0) {
        h0 = loadrow(t0 - 3); h1 = loadrow(t0 - 2); h2 = loadrow(t0 - 1);
    } else {
        h0 = make_float4(0.f, 0.f, 0.f, 0.f); h1 = h0; h2 = h0;
    }
    float4 cur = loadrow(t0);

#pragma unroll 4
    for (int i = 0; i < CONV_T; i++) {
        float4 nxt = make_float4(0.f, 0.f, 0.f, 0.f);
        if (i + 1 < CONV_T) nxt = loadrow(t0 + i + 1);

        float a0 = bias.x, a1 = bias.y, a2 = bias.z, a3 = bias.w;
        a0 = fmaf(w[0][0], h0.x, a0); a0 = fmaf(w[0][1], h1.x, a0);
        a0 = fmaf(w[0][2], h2.x, a0); a0 = fmaf(w[0][3], cur.x, a0);
        a1 = fmaf(w[1][0], h0.y, a1); a1 = fmaf(w[1][1], h1.y, a1);
        a1 = fmaf(w[1][2], h2.y, a1); a1 = fmaf(w[1][3], cur.y, a1);
        a2 = fmaf(w[2][0], h0.z, a2); a2 = fmaf(w[2][1], h1.z, a2);
        a2 = fmaf(w[2][2], h2.z, a2); a2 = fmaf(w[2][3], cur.z, a2);
        a3 = fmaf(w[3][0], h0.w, a3); a3 = fmaf(w[3][1], h1.w, a3);
        a3 = fmaf(w[3][2], h2.w, a3); a3 = fmaf(w[3][3], cur.w, a3);

        float o0 = a0 / (1.f + expf(-a0));
        float o1 = a1 / (1.f + expf(-a1));
        float o2 = a2 / (1.f + expf(-a2));
        float o3 = a3 / (1.f + expf(-a3));

        __half* hp = g_xah + (size_t)(t0 + i) * DINNER + c;
        *reinterpret_cast<__half2*>(hp)     = __floats2half2_rn(o0, o1);
        *reinterpret_cast<__half2*>(hp + 2) = __floats2half2_rn(o2, o3);

        if (c4 < 16) {
            float s = o0 + o1 + o2 + o3;
#pragma unroll
            for (int o = 8; o; o >>= 1) s += __shfl_down_sync(0xffffu, s, o);
            if (c4 == 0) g_u[t0 + i] = s * (1.f / 64.f);
        }
        h0 = h1; h1 = h2; h2 = cur; cur = nxt;
    }
}

// ======================= fused 3-phase scan (grid=BATCH, block=512) ==========
__global__ void scan_kernel()
{
    __shared__ float sA[NCHUNK][DSTATE];
    __shared__ float sV[NCHUNK][DSTATE];
    __shared__ float sC[NCHUNK][DSTATE];
    const int b = blockIdx.x;
    const int tid = threadIdx.x;
    const int c = tid >> 4;
    const int n = tid & 15;
    const size_t base = ((size_t)b * SEQLEN + (size_t)c * SCHUNK) * DSTATE + n;

    float A = 1.f, V = 0.f;
#pragma unroll 8
    for (int i = 0; i < SCHUNK; i++) {
        float a = g_adisc[base + (size_t)i * DSTATE];
        float v = g_bu   [base + (size_t)i * DSTATE];
        V = fmaf(a, V, v);
        A *= a;
    }
    sA[c][n] = A; sV[c][n] = V;
    __syncthreads();
    if (tid < DSTATE) {
        float s = 0.f;
#pragma unroll
        for (int cc = 0; cc < NCHUNK; cc++) {
            sC[cc][tid] = s;
            s = fmaf(sA[cc][tid], s, sV[cc][tid]);
        }
    }
    __syncthreads();
    float s = sC[c][n];
#pragma unroll 8
    for (int i = 0; i < SCHUNK; i++) {
        float a = g_adisc[base + (size_t)i * DSTATE];
        float v = g_bu   [base + (size_t)i * DSTATE];
        s = fmaf(a, s, v);
        g_y[base + (size_t)i * DSTATE] = s;
    }
}

// ======================= gate + skip -> fp16 y_full ===========================
__global__ void elt_kernel(const float* __restrict__ Dp, int m_off)
{
    int idx = blockIdx.x * blockDim.x + threadIdx.x;
    int c4 = idx & (DINNER/4 - 1);
    int m  = m_off + (idx >> 8);
    int c  = c4 * 4;
    float yv  = g_y[(size_t)m * DSTATE + (c >> 6)];
    const __half* xp = g_xah + (size_t)m * DINNER + c;
    float2 x0 = __half22float2(*reinterpret_cast<const __half2*>(xp));
    float2 x1 = __half22float2(*reinterpret_cast<const __half2*>(xp + 2));
    float4 D  = *reinterpret_cast<const float4*>(Dp + c);
    const __half* rp = g_resh + (size_t)m * DINNER + c;
    float2 r0 = __half22float2(*reinterpret_cast<const __half2*>(rp));
    float2 r1 = __half22float2(*reinterpret_cast<const __half2*>(rp + 2));
    float o0 = (yv + x0.x * D.x) * r0.x;
    float o1 = (yv + x0.y * D.y) * r0.y;
    float o2 = (yv + x1.x * D.z) * r1.x;
    float o3 = (yv + x1.y * D.w) * r1.y;
    __half* row = g_yh + (size_t)m * DINNER + c;
    *reinterpret_cast<__half2*>(row)     = __floats2half2_rn(o0, o1);
    *reinterpret_cast<__half2*>(row + 2) = __floats2half2_rn(o2, o3);
}

// ======================= launch ==============================================
extern "C" void kernel_launch(void* const* d_in, const int* in_sizes, int n_in,
                              void* d_out, int out_size)
{
    const float* x      = (const float*)d_in[0];
    const float* W_in   = (const float*)d_in[1];
    const float* conv_w = (const float*)d_in[2];
    const float* conv_b = (const float*)d_in[3];
    const float* W_x    = (const float*)d_in[4];
    const float* W_dt   = (const float*)d_in[5];
    const float* b_dt   = (const float*)d_in[6];
    const float* A_log  = (const float*)d_in[7];
    const float* D_par  = (const float*)d_in[8];
    const float* W_out  = (const float*)d_in[9];
    float* out = (float*)d_out;

    __half* xh;  cudaGetSymbolAddress((void**)&xh,  g_xh);
    __half* xah; cudaGetSymbolAddress((void**)&xah, g_xah);
    __half* yh;  cudaGetSymbolAddress((void**)&yh,  g_yh);
    __half* wih; cudaGetSymbolAddress((void**)&wih, g_wih);
    __half* woh; cudaGetSymbolAddress((void**)&woh, g_woh);
    __half* wch; cudaGetSymbolAddress((void**)&wch, g_wch);

    cudaFuncSetAttribute(gemm_hmma<0>, cudaFuncAttributeMaxDynamicSharedMemorySize, GH_SMEM);
    cudaFuncSetAttribute(gemm_hmma<1>, cudaFuncAttributeMaxDynamicSharedMemorySize, GH_SMEM);
    cudaFuncSetAttribute(gemm_hmma<2>, cudaFuncAttributeMaxDynamicSharedMemorySize, GH_SMEM);
    cudaFuncSetAttribute(gemm_small,   cudaFuncAttributeMaxDynamicSharedMemorySize, GS_SMEM);

    cudaStream_t s2;
    cudaStreamCreateWithFlags(&s2, cudaStreamNonBlocking);
    cudaEvent_t ev0, evW, evA, evB, evScan, evE1;
    cudaEventCreateWithFlags(&ev0,    cudaEventDisableTiming);
    cudaEventCreateWithFlags(&evW,    cudaEventDisableTiming);
    cudaEventCreateWithFlags(&evA,    cudaEventDisableTiming);
    cudaEventCreateWithFlags(&evB,    cudaEventDisableTiming);
    cudaEventCreateWithFlags(&evScan, cudaEventDisableTiming);
    cudaEventCreateWithFlags(&evE1,   cudaEventDisableTiming);

    cudaEventRecord(ev0, 0);
    cudaStreamWaitEvent(s2, ev0, 0);
    prep_w_kernel<<<1568, 256, 0, s2>>>(W_in, W_out, W_x, W_dt);
    cudaEventRecord(evW, s2);

    prep_x_kernel<<<(M_TOK*DIM)/1024, 256>>>(x);
    cudaStreamWaitEvent(0, evW, 0);

    // GEMM1a: xi half -> g_xih
    gemm_hmma<1><<<dim3(DINNER/128, M_TOK/128), 256, GH_SMEM>>>(
        xh, wih, nullptr, 0, DIM, 0);

    // fork: GEMM1b res half on s2 (silu -> g_resh)
    cudaEventRecord(evA, 0);
    cudaStreamWaitEvent(s2, evA, 0);
    gemm_hmma<2><<<dim3(DINNER/128, M_TOK/128), 256, GH_SMEM, s2>>>(
        xh, wih + (size_t)DINNER * DIM, nullptr, 0, DIM, 0);
    cudaEventRecord(evB, s2);

    // dependent chain on main (overlaps GEMM1b)
    conv_silu_kernel<<<M_TOK/CONV_T, 256>>>(conv_w, conv_b);
    gemm_small<<<M_TOK/128, 256, GS_SMEM>>>(xah, wch, b_dt, A_log);
    scan_kernel<<<BATCH, 512>>>();
    cudaEventRecord(evScan, 0);

    // tail split: elt_h0 on main; elt_h1 on s2
    cudaStreamWaitEvent(0, evB, 0);
    elt_kernel<<<(M_TOK/2)*(DINNER/4)/256, 256>>>(D_par, 0);
    cudaStreamWaitEvent(s2, evScan, 0);
    elt_kernel<<<(M_TOK/2)*(DINNER/4)/256, 256, 0, s2>>>(D_par, M_TOK/2);
    cudaEventRecord(evE1, s2);

    // GEMM2 halves: h0 overlaps elt_h1
    gemm_hmma<0><<<dim3(DIM/128, M_TOK/256), 256, GH_SMEM>>>(
        yh, woh, out, DIM, DINNER, 0);
    cudaStreamWaitEvent(0, evE1, 0);
    gemm_hmma<0><<<dim3(DIM/128, M_TOK/256), 256, GH_SMEM>>>(
        yh, woh, out, DIM, DINNER, M_TOK/2);
}

// round 16
// speedup vs baseline: 1.0775x; 1.0775x over previous
#include <cuda_runtime.h>
#include <cuda_fp16.h>
#include <math.h>
#include <stdint.h>

#define BATCH   4
#define SEQLEN  4096
#define DIM     512
#define DINNER  1024
#define DSTATE  16
#define DCONV   4
#define M_TOK   (BATCH*SEQLEN)   // 16384

// ======================= PTX helpers (sm_80 baseline) ========================
__device__ __forceinline__ uint32_t smem_to_u32(const void* p) {
    uint32_t a;
    asm("{ .reg .u64 t; cvta.to.shared.u64 t, %1; cvt.u32.u64 %0, t; }"
        : "=r"(a) : "l"(p));
    return a;
}
#define CP_ASYNC16(saddr, gptr) \
    asm volatile("cp.async.cg.shared.global [%0], [%1], 16;" \
        :: "r"(saddr), "l"(gptr))
#define CP_COMMIT() asm volatile("cp.async.commit_group;" ::: "memory")
#define CP_WAIT1()  asm volatile("cp.async.wait_group 1;" ::: "memory")
#define CP_WAIT0()  asm volatile("cp.async.wait_group 0;" ::: "memory")

#define LDSM_X4(r, addr) \
    asm volatile("ldmatrix.sync.aligned.m8n8.x4.shared.b16 {%0,%1,%2,%3}, [%4];" \
        : "=r"((r)[0]), "=r"((r)[1]), "=r"((r)[2]), "=r"((r)[3]) : "r"(addr))

#define MMA_F16(d, a, b0, b1) \
    asm volatile("mma.sync.aligned.m16n8k16.row.col.f32.f16.f16.f32 " \
        "{%0,%1,%2,%3}, {%4,%5,%6,%7}, {%8,%9}, {%0,%1,%2,%3};" \
        : "+f"((d)[0]), "+f"((d)[1]), "+f"((d)[2]), "+f"((d)[3]) \
        : "r"((a)[0]), "r"((a)[1]), "r"((a)[2]), "r"((a)[3]), "r"(b0), "r"(b1))

// ======================= scratch =============================================
__device__ __align__(256) float  g_u   [M_TOK];
__device__ __align__(256) float  g_adisc[(size_t)M_TOK * DSTATE];
__device__ __align__(256) float  g_bu  [(size_t)M_TOK * DSTATE];
__device__ __align__(256) float  g_y   [(size_t)M_TOK * DSTATE];
// fp16 planes
__device__ __align__(256) __half g_xh  [(size_t)M_TOK * DIM];
__device__ __align__(256) __half g_xih [(size_t)M_TOK * DINNER];
__device__ __align__(256) __half g_resh[(size_t)M_TOK * DINNER];
__device__ __align__(256) __half g_xah [(size_t)M_TOK * DINNER];
__device__ __align__(256) __half g_yh  [(size_t)M_TOK * DINNER];
__device__ __align__(256) __half g_wih [(size_t)2*DINNER * DIM];
__device__ __align__(256) __half g_woh [(size_t)DIM * DINNER];
__device__ __align__(256) __half g_wch [2 * DSTATE * DINNER];
// scan constants
#define SCHUNK  128
#define NCHUNK  (SEQLEN / SCHUNK)   // 32

// ======================= HMMA fp16 GEMM (XOR-swizzled smem) ==================
// Block tile 128x128, 256 threads (8 warps 4x2, warp tile 32x64),
// K-chunk 64, 3-stage cp.async pipeline, 1 sync/chunk.
// Smem rows are 128B with XOR swizzle: chunk cc of row r stored at
// (cc ^ (r&7))*16 -> ldmatrix phases are bank-conflict-free.
// MODE 0: fp32 C. MODE 1: write g_xih. MODE 2: silu -> g_resh.
#define A_TILE_B  16384                     // 128 rows x 128B
#define B_OFF_B   16384
#define STAGE_B   32768
#define GH_SMEM   (3 * STAGE_B)             // 98304

template<int MODE>
__global__ __launch_bounds__(256, 2)
void gemm_hmma(const __half* __restrict__ A, const __half* __restrict__ B,
               float* __restrict__ C, int Nglob, int K, int m_off)
{
    extern __shared__ char smem[];
    const uint32_t sb = smem_to_u32(smem);
    const int tid  = threadIdx.x;
    const int wid  = tid >> 5;
    const int lane = tid & 31;
    const int m0 = m_off + blockIdx.y * 128;
    const int n0 = blockIdx.x * 128;
    const int nch = K / 64;

    const int wm = (wid & 3) * 32;
    const int wn = (wid >> 2) * 64;

    float acc[2][8][4];
#pragma unroll
    for (int i = 0; i < 2; i++)
#pragma unroll
        for (int j = 0; j < 8; j++)
#pragma unroll
            for (int k = 0; k < 4; k++) acc[i][j][k] = 0.f;

    // ---- cp.async: row r, chunk cc -> smem r*128 + ((cc^(r&7))<<4) ----------
    const int ld_row = tid >> 3, ld_cc = tid & 7;
    const __half* pA = A + (size_t)(m0 + ld_row) * K + ld_cc * 8;
    const __half* pB = B + (size_t)(n0 + ld_row) * K + ld_cc * 8;
    const uint32_t dstA = sb + (uint32_t)(ld_row * 128 + ((ld_cc ^ (ld_row & 7)) << 4));
    const uint32_t dstB = dstA + B_OFF_B;

    auto issue = [&](int s) {
        const uint32_t so = (uint32_t)(s * STAGE_B);
#pragma unroll
        for (int i = 0; i < 4; i++) {   // +32 rows per i: (r&7) unchanged
            CP_ASYNC16(dstA + so + (uint32_t)(i * 32 * 128), pA + (size_t)i * 32 * K);
            CP_ASYNC16(dstB + so + (uint32_t)(i * 32 * 128), pB + (size_t)i * 32 * K);
        }
        CP_COMMIT();
        pA += 64; pB += 64;
    };

    issue(0);
    if (nch > 1) issue(1);

    // ---- ldmatrix addressing: row offsets + swizzled chunk position ---------
    const int lrow = lane & 15;
    const int hi   = lane >> 4;
    const int r7   = lrow & 7;          // (wm+mt*16+lrow)&7 == lrow&7
    uint32_t pos[4];
#pragma unroll
    for (int ks = 0; ks < 4; ks++)
        pos[ks] = (uint32_t)(((((ks * 2) | hi) ^ r7)) << 4);
    const uint32_t aR0 = (uint32_t)((wm + lrow) * 128);
    const uint32_t aR1 = aR0 + 16 * 128;
    const uint32_t bR0 = (uint32_t)(B_OFF_B + (wn + lrow) * 128);
    const uint32_t bR1 = bR0 + 2048, bR2 = bR0 + 4096, bR3 = bR0 + 6144;

    uint32_t stOff = 0;
    for (int c = 0; c < nch; c++) {
        if (c + 1 < nch) { CP_WAIT1(); } else { CP_WAIT0(); }
        __syncthreads();

        const uint32_t base = sb + stOff;
        if (c + 2 < nch) {
            int s2 = stOff == 0 ? 2 : (stOff == STAGE_B ? 0 : 1);
            issue(s2);
        }
#pragma unroll
        for (int ks = 0; ks < 4; ks++) {
            uint32_t af[2][4], bf[4][4];
            LDSM_X4(af[0], base + aR0 + pos[ks]);
            LDSM_X4(af[1], base + aR1 + pos[ks]);
            LDSM_X4(bf[0], base + bR0 + pos[ks]);
            LDSM_X4(bf[1], base + bR1 + pos[ks]);
            LDSM_X4(bf[2], base + bR2 + pos[ks]);
            LDSM_X4(bf[3], base + bR3 + pos[ks]);
#pragma unroll
            for (int mt = 0; mt < 2; mt++)
#pragma unroll
                for (int nt = 0; nt < 8; nt++) {
                    const int ng = nt >> 1, h2 = nt & 1;
                    MMA_F16(acc[mt][nt], af[mt], bf[ng][h2], bf[ng][2 + h2]);
                }
        }
        stOff = (stOff == 2 * STAGE_B) ? 0u : stOff + STAGE_B;
    }

    const int er = lane >> 2;
    const int ec = (lane & 3) * 2;
#pragma unroll
    for (int mt = 0; mt < 2; mt++) {
        const int rbase = m0 + wm + mt * 16;
#pragma unroll
        for (int nt = 0; nt < 8; nt++) {
            const int col = n0 + wn + nt * 8 + ec;
            float v0 = acc[mt][nt][0], v1 = acc[mt][nt][1];
            float v2 = acc[mt][nt][2], v3 = acc[mt][nt][3];
            if (MODE == 0) {
                *reinterpret_cast<float2*>(C + (size_t)(rbase + er)     * Nglob + col) =
                    make_float2(v0, v1);
                *reinterpret_cast<float2*>(C + (size_t)(rbase + er + 8) * Nglob + col) =
                    make_float2(v2, v3);
            } else if (MODE == 1) {
                *reinterpret_cast<__half2*>(g_xih + (size_t)(rbase + er)     * DINNER + col) =
                    __floats2half2_rn(v0, v1);
                *reinterpret_cast<__half2*>(g_xih + (size_t)(rbase + er + 8) * DINNER + col) =
                    __floats2half2_rn(v2, v3);
            } else {
                v0 = v0 / (1.f + expf(-v0));
                v1 = v1 / (1.f + expf(-v1));
                v2 = v2 / (1.f + expf(-v2));
                v3 = v3 / (1.f + expf(-v3));
                *reinterpret_cast<__half2*>(g_resh + (size_t)(rbase + er)     * DINNER + col) =
                    __floats2half2_rn(v0, v1);
                *reinterpret_cast<__half2*>(g_resh + (size_t)(rbase + er + 8) * DINNER + col) =
                    __floats2half2_rn(v2, v3);
            }
        }
    }
}

// ============== small HMMA GEMM fused with dt/A_disc/Bu epilogue =============
// B resident (32 rows x 2048B, XOR-swizzled per 128B segment); A 3-stage.
#define SB_BYTES  (32 * 2048)                 // 65536
#define SA_TILE   16384
#define GS_SMEM   (SB_BYTES + 3 * SA_TILE)    // 114688

__global__ __launch_bounds__(256, 1)
void gemm_small(const __half* __restrict__ A, const __half* __restrict__ B,
                const float* __restrict__ bdt, const float* __restrict__ Alog)
{
    extern __shared__ char smem[];
    const uint32_t sb = smem_to_u32(smem);
    const int tid  = threadIdx.x;
    const int wid  = tid >> 5;
    const int lane = tid & 31;
    const int m0 = blockIdx.x * 128;
    const int K = DINNER;
    const int nch = K / 64;

    {
#pragma unroll
        for (int i = 0; i < 16; i++) {
            int idx = tid + i * 256;
            int row = idx >> 7, cc = idx & 127;
            uint32_t dst = (uint32_t)(row * 2048 + ((cc ^ (row & 7)) << 4));
            CP_ASYNC16(sb + dst, B + (size_t)row * K + cc * 8);
        }
        CP_COMMIT();
    }

    const int ld_row = tid >> 3, ld_cc = tid & 7;
    const __half* pA = A + (size_t)(m0 + ld_row) * K + ld_cc * 8;
    const uint32_t dstA = sb + (uint32_t)(SB_BYTES + ld_row * 128 +
                                          ((ld_cc ^ (ld_row & 7)) << 4));

    auto issueA = [&](int s) {
        const uint32_t so = (uint32_t)(s * SA_TILE);
#pragma unroll
        for (int i = 0; i < 4; i++)
            CP_ASYNC16(dstA + so + (uint32_t)(i * 32 * 128), pA + (size_t)i * 32 * K);
        CP_COMMIT();
        pA += 64;
    };

    const int wm = wid * 16;
    float acc[4][4];
#pragma unroll
    for (int j = 0; j < 4; j++)
#pragma unroll
        for (int k = 0; k < 4; k++) acc[j][k] = 0.f;

    issueA(0);
    issueA(1);

    const int lrow = lane & 15;
    const int hi   = lane >> 4;
    const int r7   = lrow & 7;
    uint32_t pos[4];
#pragma unroll
    for (int ks = 0; ks < 4; ks++)
        pos[ks] = (uint32_t)(((((ks * 2) | hi) ^ r7)) << 4);
    const uint32_t aR = (uint32_t)(SB_BYTES + (wm + lrow) * 128);
    const uint32_t bRow0 = (uint32_t)(lrow * 2048);
    const uint32_t bRow1 = bRow0 + 16 * 2048;

    int stage = 0;
    for (int c = 0; c < nch; c++) {
        if (c + 1 < nch) { CP_WAIT1(); } else { CP_WAIT0(); }
        __syncthreads();

        const uint32_t aBase = sb + (uint32_t)(stage * SA_TILE);
        if (c + 2 < nch) issueA((stage + 2) % 3);
        const uint32_t cOff = (uint32_t)(c * 128);   // c*8 chunks * 16B
#pragma unroll
        for (int ks = 0; ks < 4; ks++) {
            uint32_t af[4], bfr[2][4];
            LDSM_X4(af, aBase + aR + pos[ks]);
            LDSM_X4(bfr[0], sb + bRow0 + cOff + pos[ks]);
            LDSM_X4(bfr[1], sb + bRow1 + cOff + pos[ks]);
#pragma unroll
            for (int nt = 0; nt < 4; nt++) {
                const int ng = nt >> 1, h2 = nt & 1;
                MMA_F16(acc[nt], af, bfr[ng][h2], bfr[ng][2 + h2]);
            }
        }
        stage = (stage + 1) % 3;
    }

    const int er = lane >> 2;
    const int ec = (lane & 3) * 2;
    const int r0 = m0 + wm + er;
    const float u0 = g_u[r0];
    const float u1 = g_u[r0 + 8];
#pragma unroll
    for (int nt = 0; nt < 2; nt++) {
#pragma unroll
        for (int j = 0; j < 2; j++) {
            const int n = nt * 8 + ec + j;
            const float Av = -expf(Alog[n]);
            const float bn = bdt[n];
            {
                float raw = acc[nt][j] + bn;
                float dt  = raw > 20.f ? raw : log1pf(expf(raw));
                g_adisc[(size_t)r0 * DSTATE + n] = expf(Av * dt);
                g_bu   [(size_t)r0 * DSTATE + n] = dt * acc[nt + 2][j] * u0;
            }
            {
                float raw = acc[nt][2 + j] + bn;
                float dt  = raw > 20.f ? raw : log1pf(expf(raw));
                g_adisc[(size_t)(r0 + 8) * DSTATE + n] = expf(Av * dt);
                g_bu   [(size_t)(r0 + 8) * DSTATE + n] = dt * acc[nt + 2][2 + j] * u1;
            }
        }
    }
}

// ======================= prep kernels ========================================
__global__ void prep_x_kernel(const float* __restrict__ x)
{
    long i = ((long)blockIdx.x * 256 + threadIdx.x) * 4;
    float4 v = *reinterpret_cast<const float4*>(x + i);
    *reinterpret_cast<__half2*>(g_xh + i)     = __floats2half2_rn(v.x, v.y);
    *reinterpret_cast<__half2*>(g_xh + i + 2) = __floats2half2_rn(v.z, v.w);
}
__global__ void prep_w_kernel(const float* __restrict__ W_in, const float* __restrict__ W_out,
                              const float* __restrict__ Wx, const float* __restrict__ Wdt)
{
    const int b = blockIdx.x;
    if (b < 1024) {
        long i = ((long)b * 256 + threadIdx.x) * 4;
        float4 v = *reinterpret_cast<const float4*>(W_in + i);
        *reinterpret_cast<__half2*>(g_wih + i)     = __floats2half2_rn(v.x, v.y);
        *reinterpret_cast<__half2*>(g_wih + i + 2) = __floats2half2_rn(v.z, v.w);
    } else if (b < 1536) {
        long i = ((long)(b - 1024) * 256 + threadIdx.x) * 4;
        float4 v = *reinterpret_cast<const float4*>(W_out + i);
        *reinterpret_cast<__half2*>(g_woh + i)     = __floats2half2_rn(v.x, v.y);
        *reinterpret_cast<__half2*>(g_woh + i + 2) = __floats2half2_rn(v.z, v.w);
    } else {
        int i = (b - 1536) * 1024 + threadIdx.x * 4;
        int row = i >> 10;
        const float* src = (row < DSTATE) ? Wdt : Wx;
        float4 v = *reinterpret_cast<const float4*>(src + i);
        *reinterpret_cast<__half2*>(g_wch + i)     = __floats2half2_rn(v.x, v.y);
        *reinterpret_cast<__half2*>(g_wch + i + 2) = __floats2half2_rn(v.z, v.w);
    }
}

// ======================= conv: rolling window, coalesced =====================
#define CONV_T 32
__global__ __launch_bounds__(256)
void conv_silu_kernel(const float* __restrict__ cw, const float* __restrict__ cb)
{
    const int c4 = threadIdx.x;
    const int c  = c4 * 4;
    const int t0 = blockIdx.x * CONV_T;
    const int l0 = t0 & (SEQLEN - 1);

    float w[4][4];
#pragma unroll
    for (int j = 0; j < 4; j++)
        *reinterpret_cast<float4*>(w[j]) =
            *reinterpret_cast<const float4*>(cw + (size_t)(c + j) * DCONV);
    const float4 bias = *reinterpret_cast<const float4*>(cb + c);

    auto loadrow = [&](int t) -> float4 {
        const __half* xp = g_xih + (size_t)t * DINNER + c;
        float2 f0 = __half22float2(*reinterpret_cast<const __half2*>(xp));
        float2 f1 = __half22float2(*reinterpret_cast<const __half2*>(xp + 2));
        return make_float4(f0.x, f0.y, f1.x, f1.y);
    };

    float4 h0, h1, h2;
    if (l0 != 0) {
        h0 = loadrow(t0 - 3); h1 = loadrow(t0 - 2); h2 = loadrow(t0 - 1);
    } else {
        h0 = make_float4(0.f, 0.f, 0.f, 0.f); h1 = h0; h2 = h0;
    }
    float4 cur = loadrow(t0);

#pragma unroll 4
    for (int i = 0; i < CONV_T; i++) {
        float4 nxt = make_float4(0.f, 0.f, 0.f, 0.f);
        if (i + 1 < CONV_T) nxt = loadrow(t0 + i + 1);

        float a0 = bias.x, a1 = bias.y, a2 = bias.z, a3 = bias.w;
        a0 = fmaf(w[0][0], h0.x, a0); a0 = fmaf(w[0][1], h1.x, a0);
        a0 = fmaf(w[0][2], h2.x, a0); a0 = fmaf(w[0][3], cur.x, a0);
        a1 = fmaf(w[1][0], h0.y, a1); a1 = fmaf(w[1][1], h1.y, a1);
        a1 = fmaf(w[1][2], h2.y, a1); a1 = fmaf(w[1][3], cur.y, a1);
        a2 = fmaf(w[2][0], h0.z, a2); a2 = fmaf(w[2][1], h1.z, a2);
        a2 = fmaf(w[2][2], h2.z, a2); a2 = fmaf(w[2][3], cur.z, a2);
        a3 = fmaf(w[3][0], h0.w, a3); a3 = fmaf(w[3][1], h1.w, a3);
        a3 = fmaf(w[3][2], h2.w, a3); a3 = fmaf(w[3][3], cur.w, a3);

        float o0 = a0 / (1.f + expf(-a0));
        float o1 = a1 / (1.f + expf(-a1));
        float o2 = a2 / (1.f + expf(-a2));
        float o3 = a3 / (1.f + expf(-a3));

        __half* hp = g_xah + (size_t)(t0 + i) * DINNER + c;
        *reinterpret_cast<__half2*>(hp)     = __floats2half2_rn(o0, o1);
        *reinterpret_cast<__half2*>(hp + 2) = __floats2half2_rn(o2, o3);

        if (c4 < 16) {
            float s = o0 + o1 + o2 + o3;
#pragma unroll
            for (int o = 8; o; o >>= 1) s += __shfl_down_sync(0xffffu, s, o);
            if (c4 == 0) g_u[t0 + i] = s * (1.f / 64.f);
        }
        h0 = h1; h1 = h2; h2 = cur; cur = nxt;
    }
}

// ======================= fused 3-phase scan (grid=BATCH, block=512) ==========
__global__ void scan_kernel()
{
    __shared__ float sA[NCHUNK][DSTATE];
    __shared__ float sV[NCHUNK][DSTATE];
    __shared__ float sC[NCHUNK][DSTATE];
    const int b = blockIdx.x;
    const int tid = threadIdx.x;
    const int c = tid >> 4;
    const int n = tid & 15;
    const size_t base = ((size_t)b * SEQLEN + (size_t)c * SCHUNK) * DSTATE + n;

    float A = 1.f, V = 0.f;
#pragma unroll 8
    for (int i = 0; i < SCHUNK; i++) {
        float a = g_adisc[base + (size_t)i * DSTATE];
        float v = g_bu   [base + (size_t)i * DSTATE];
        V = fmaf(a, V, v);
        A *= a;
    }
    sA[c][n] = A; sV[c][n] = V;
    __syncthreads();
    if (tid < DSTATE) {
        float s = 0.f;
#pragma unroll
        for (int cc = 0; cc < NCHUNK; cc++) {
            sC[cc][tid] = s;
            s = fmaf(sA[cc][tid], s, sV[cc][tid]);
        }
    }
    __syncthreads();
    float s = sC[c][n];
#pragma unroll 8
    for (int i = 0; i < SCHUNK; i++) {
        float a = g_adisc[base + (size_t)i * DSTATE];
        float v = g_bu   [base + (size_t)i * DSTATE];
        s = fmaf(a, s, v);
        g_y[base + (size_t)i * DSTATE] = s;
    }
}

// ======================= gate + skip -> fp16 y_full ===========================
__global__ void elt_kernel(const float* __restrict__ Dp, int m_off)
{
    int idx = blockIdx.x * blockDim.x + threadIdx.x;
    int c4 = idx & (DINNER/4 - 1);
    int m  = m_off + (idx >> 8);
    int c  = c4 * 4;
    float yv  = g_y[(size_t)m * DSTATE + (c >> 6)];
    const __half* xp = g_xah + (size_t)m * DINNER + c;
    float2 x0 = __half22float2(*reinterpret_cast<const __half2*>(xp));
    float2 x1 = __half22float2(*reinterpret_cast<const __half2*>(xp + 2));
    float4 D  = *reinterpret_cast<const float4*>(Dp + c);
    const __half* rp = g_resh + (size_t)m * DINNER + c;
    float2 r0 = __half22float2(*reinterpret_cast<const __half2*>(rp));
    float2 r1 = __half22float2(*reinterpret_cast<const __half2*>(rp + 2));
    float o0 = (yv + x0.x * D.x) * r0.x;
    float o1 = (yv + x0.y * D.y) * r0.y;
    float o2 = (yv + x1.x * D.z) * r1.x;
    float o3 = (yv + x1.y * D.w) * r1.y;
    __half* row = g_yh + (size_t)m * DINNER + c;
    *reinterpret_cast<__half2*>(row)     = __floats2half2_rn(o0, o1);
    *reinterpret_cast<__half2*>(row + 2) = __floats2half2_rn(o2, o3);
}

// ======================= launch ==============================================
extern "C" void kernel_launch(void* const* d_in, const int* in_sizes, int n_in,
                              void* d_out, int out_size)
{
    const float* x      = (const float*)d_in[0];
    const float* W_in   = (const float*)d_in[1];
    const float* conv_w = (const float*)d_in[2];
    const float* conv_b = (const float*)d_in[3];
    const float* W_x    = (const float*)d_in[4];
    const float* W_dt   = (const float*)d_in[5];
    const float* b_dt   = (const float*)d_in[6];
    const float* A_log  = (const float*)d_in[7];
    const float* D_par  = (const float*)d_in[8];
    const float* W_out  = (const float*)d_in[9];
    float* out = (float*)d_out;

    __half* xh;  cudaGetSymbolAddress((void**)&xh,  g_xh);
    __half* xah; cudaGetSymbolAddress((void**)&xah, g_xah);
    __half* yh;  cudaGetSymbolAddress((void**)&yh,  g_yh);
    __half* wih; cudaGetSymbolAddress((void**)&wih, g_wih);
    __half* woh; cudaGetSymbolAddress((void**)&woh, g_woh);
    __half* wch; cudaGetSymbolAddress((void**)&wch, g_wch);

    cudaFuncSetAttribute(gemm_hmma<0>, cudaFuncAttributeMaxDynamicSharedMemorySize, GH_SMEM);
    cudaFuncSetAttribute(gemm_hmma<1>, cudaFuncAttributeMaxDynamicSharedMemorySize, GH_SMEM);
    cudaFuncSetAttribute(gemm_hmma<2>, cudaFuncAttributeMaxDynamicSharedMemorySize, GH_SMEM);
    cudaFuncSetAttribute(gemm_small,   cudaFuncAttributeMaxDynamicSharedMemorySize, GS_SMEM);

    cudaStream_t s2;
    cudaStreamCreateWithFlags(&s2, cudaStreamNonBlocking);
    cudaEvent_t ev0, evW, evA, evB, evScan, evE1;
    cudaEventCreateWithFlags(&ev0,    cudaEventDisableTiming);
    cudaEventCreateWithFlags(&evW,    cudaEventDisableTiming);
    cudaEventCreateWithFlags(&evA,    cudaEventDisableTiming);
    cudaEventCreateWithFlags(&evB,    cudaEventDisableTiming);
    cudaEventCreateWithFlags(&evScan, cudaEventDisableTiming);
    cudaEventCreateWithFlags(&evE1,   cudaEventDisableTiming);

    cudaEventRecord(ev0, 0);
    cudaStreamWaitEvent(s2, ev0, 0);
    prep_w_kernel<<<1568, 256, 0, s2>>>(W_in, W_out, W_x, W_dt);
    cudaEventRecord(evW, s2);

    prep_x_kernel<<<(M_TOK*DIM)/1024, 256>>>(x);
    cudaStreamWaitEvent(0, evW, 0);

    // GEMM1a: xi half -> g_xih
    gemm_hmma<1><<<dim3(DINNER/128, M_TOK/128), 256, GH_SMEM>>>(
        xh, wih, nullptr, 0, DIM, 0);

    // fork: GEMM1b res half on s2 (silu -> g_resh)
    cudaEventRecord(evA, 0);
    cudaStreamWaitEvent(s2, evA, 0);
    gemm_hmma<2><<<dim3(DINNER/128, M_TOK/128), 256, GH_SMEM, s2>>>(
        xh, wih + (size_t)DINNER * DIM, nullptr, 0, DIM, 0);
    cudaEventRecord(evB, s2);

    // dependent chain on main (overlaps GEMM1b)
    conv_silu_kernel<<<M_TOK/CONV_T, 256>>>(conv_w, conv_b);
    gemm_small<<<M_TOK/128, 256, GS_SMEM>>>(xah, wch, b_dt, A_log);
    scan_kernel<<<BATCH, 512>>>();
    cudaEventRecord(evScan, 0);

    // tail split: elt_h0 on main; elt_h1 on s2
    cudaStreamWaitEvent(0, evB, 0);
    elt_kernel<<<(M_TOK/2)*(DINNER/4)/256, 256>>>(D_par, 0);
    cudaStreamWaitEvent(s2, evScan, 0);
    elt_kernel<<<(M_TOK/2)*(DINNER/4)/256, 256, 0, s2>>>(D_par, M_TOK/2);
    cudaEventRecord(evE1, s2);

    // GEMM2 halves: h0 overlaps elt_h1
    gemm_hmma<0><<<dim3(DIM/128, M_TOK/256), 256, GH_SMEM>>>(
        yh, woh, out, DIM, DINNER, 0);
    cudaStreamWaitEvent(0, evE1, 0);
    gemm_hmma<0><<<dim3(DIM/128, M_TOK/256), 256, GH_SMEM>>>(
        yh, woh, out, DIM, DINNER, M_TOK/2);
}